// round 14
// baseline (speedup 1.0000x reference)
#include <cuda_runtime.h>

#define NS    53       // species
#define ND    54       // state dim
#define NRX   325      // reactions
#define FCAP  1024     // fwd CSR entries cap (expected ~690)
#define NCAP  2048     // net CSR entries cap (expected ~1365)
#define BD    160      // threads per block
#define RGAS  8.314462618f

// ---- CSRs built once per launch. Stoichiometry is exactly 0/1:
//      fwd lists carry no values; net lists are split pos-run / neg-run ----
__device__ int   g_foff[NRX + 1];
__device__ short g_fent[FCAP];
__device__ int   g_noff[NS + 1];
__device__ int   g_nmid[NS];
__device__ short g_nent[NCAP];

__global__ void prep_csr_kernel(const float* __restrict__ nuf,
                                const float* __restrict__ nub) {
    __shared__ int scf[NRX], scp[NS], scn[NS];
    const int tid = threadIdx.x;   // single block, 256 threads
    for (int j = tid; j < NRX; j += 256) {
        int c = 0;
        for (int k = 0; k < NS; k++)
            if (nuf[j * NS + k] != 0.0f) c++;
        scf[j] = c;
    }
    for (int s = tid; s < NS; s += 256) {
        int cp = 0, cn = 0;
        for (int j = 0; j < NRX; j++) {
            float net = nub[j * NS + s] - nuf[j * NS + s];
            cp += (net > 0.0f);
            cn += (net < 0.0f);
        }
        scp[s] = cp; scn[s] = cn;
    }
    __syncthreads();
    if (tid == 0) {
        int run = 0;
        for (int i = 0; i < NRX; i++) { g_foff[i] = run; run += scf[i]; }
        g_foff[NRX] = run;
    }
    if (tid == 32) {
        int run = 0;
        for (int i = 0; i < NS; i++) {
            g_noff[i] = run;
            g_nmid[i] = run + scp[i];
            run += scp[i] + scn[i];
        }
        g_noff[NS] = run;
    }
    __syncthreads();
    for (int j = tid; j < NRX; j += 256) {
        int w = g_foff[j];
        for (int k = 0; k < NS; k++)
            if (nuf[j * NS + k] != 0.0f && w < FCAP) g_fent[w++] = (short)k;
    }
    for (int s = tid; s < NS; s += 256) {
        int wp = g_noff[s], wn = g_nmid[s];
        for (int j = 0; j < NRX; j++) {
            float net = nub[j * NS + s] - nuf[j * NS + s];
            if (net > 0.0f && wp < NCAP) g_nent[wp++] = (short)j;
            else if (net < 0.0f && wn < NCAP) g_nent[wn++] = (short)j;
        }
    }
}

__device__ __forceinline__ float wred53(const float* a, int lane) {
    float s = (lane < NS ? a[lane] : 0.0f)
            + (lane + 32 < NS ? a[lane + 32] : 0.0f);
    #pragma unroll
    for (int o = 16; o; o >>= 1) s += __shfl_xor_sync(0xffffffffu, s, o);
    return s;
}

__global__ __launch_bounds__(BD, 7)
void reactor_kernel(const float* __restrict__ T0,  const float* __restrict__ Pv,
                    const float* __restrict__ Y0,  const float* __restrict__ Wm,
                    const float* __restrict__ nlo, const float* __restrict__ nhi,
                    const float* __restrict__ Tmid,
                    const float* __restrict__ rA,  const float* __restrict__ rB,
                    const float* __restrict__ rE,  const int* __restrict__ nstp,
                    float* __restrict__ out) {
    __shared__ float Lc[NS], gC[NS], hmol_s[NS], uu_s[NS], vv_s[NS], zz[NS];
    __shared__ float tmw[NS], tcp[NS], tdc[NS], tH[NS], thw[NS];
    __shared__ float tsig[NS], tcpx[NS], thu[NS], thv[NS], thq[NS];
    __shared__ float r_[NRX], rP_[NRX], rT_[NRX], w_[NRX];
    __shared__ unsigned short sFoff[NRX + 1];
    __shared__ short sFent[FCAP];
    __shared__ unsigned short sNoff[NS + 1];
    __shared__ unsigned short sNmid[NS];
    __shared__ short sNent[NCAP];
    __shared__ float sT, sLnT, sMT, sRho, sInvRho, sInvIMW, sYn0, sYcur0;
    __shared__ float sSig, sCpx, sG0, sHu, sC1, sC2, sC3, sC4;

    const int tid  = threadIdx.x;
    const int lane = tid & 31;
    const int b    = blockIdx.x;
    const bool own = (tid < NS);

    const float P = Pv[0];
    const int n_steps = nstp[0];
    const float dt = 1.0e-6f / (float)n_steps;

    // ---- one-time: CSRs to smem, owner state to registers ----
    for (int i = tid; i < NRX + 1; i += BD) sFoff[i] = (unsigned short)g_foff[i];
    for (int i = tid; i < FCAP; i += BD)    sFent[i] = g_fent[i];
    for (int i = tid; i < NS + 1; i += BD)  sNoff[i] = (unsigned short)g_noff[i];
    for (int i = tid; i < NS; i += BD)      sNmid[i] = (unsigned short)g_nmid[i];
    for (int i = tid; i < NCAP; i += BD)    sNent[i] = g_nent[i];

    float Y = 0.0f, ycur = 0.0f, Wsk = 1.0f, iw = 1.0f, Tmk = 0.0f;
    if (own) {
        Wsk = Wm[tid];
        iw  = 1.0f / Wsk;
        Y   = Y0[b * NS + tid];
        Tmk = Tmid[tid];
    }
    if (tid == 0) {
        float t = T0[b];
        sYn0 = t;
        float Tc = fminf(fmaxf(t, 200.0f), 5000.0f);
        sT = Tc;
        sMT = (t > 200.0f && t < 5000.0f) ? 1.0f : 0.0f;
        sLnT = logf(Tc);
    }
    __syncthreads();

    for (int step = 0; step < n_steps; ++step) {
        for (int it = 0; it < 2; ++it) {
            const float T = sT;
            const float invT = 1.0f / T;
            // per-Newton owner registers
            float Yc = 0.0f, mYk = 0.0f, cpRk = 0.0f, hmolk = 0.0f;
            float t0ak = 0.0f, Work = 0.0f, sm0k = 0.0f, cpwk = 0.0f;
            float Gk = 0.0f, wdk = 0.0f;

            // ---- P1: thermo (owners) ----
            if (own) {
                if (it == 0) ycur = Y;
                float Yr = Y;
                Yc  = fminf(fmaxf(Yr, 0.0f), 1.0f);
                mYk = (Yr > 0.0f && Yr < 1.0f) ? 1.0f : 0.0f;
                const float* a = (T < Tmk) ? (nlo + 7 * tid) : (nhi + 7 * tid);
                float a0 = a[0], a1v = a[1], a2v = a[2], a3v = a[3], a4 = a[4], a5 = a[5];
                float T2 = T * T, T3 = T2 * T, T4 = T2 * T2;
                cpRk = a0 + a1v * T + a2v * T2 + a3v * T3 + a4 * T4;
                float hRT = a0 + a1v * T * 0.5f + a2v * T2 * (1.0f / 3.0f)
                          + a3v * T3 * 0.25f + a4 * T4 * 0.2f + a5 * invT;
                hmolk = hRT * RGAS * T;
                float dcpRk = a1v + 2.0f * a2v * T + 3.0f * a3v * T2 + 4.0f * a4 * T3;
                float yw = Yc * iw;
                tmw[tid] = yw;
                tcp[tid] = yw * cpRk;
                tdc[tid] = yw * dcpRk;
                hmol_s[tid] = hmolk;
            }
            if (tid == 0 && it == 0) sYcur0 = sYn0;
            __syncthreads();

            // ---- P2: mixture reduction (warp0) ----
            if (tid < 32) {
                float s = wred53(tmw, lane);
                if (lane == 0) {
                    sInvIMW = 1.0f / s;
                    sRho = P / (RGAS * T * s);
                    sInvRho = (RGAS * T * s) / P;
                }
            }
            __syncthreads();

            // ---- P3: concentrations (owners) ----
            const float rho = sRho, invRho = sInvRho, invIMW = sInvIMW;
            if (own) {
                float C  = rho * Yc * iw;
                float Ce = C + 1e-30f;
                Lc[tid] = logf(Ce);
                gC[tid] = C / Ce;
                t0ak = rho * iw / Ce;
                Work = Wsk * invRho;
                sm0k = -invIMW * iw;
                cpwk = cpRk * RGAS * iw * mYk;
            }
            __syncthreads();

            // ---- P4: rates (all threads); single fused exp ----
            const float invRT = 1.0f / (RGAS * T);
            for (int j = tid; j < NRX; j += BD) {
                float Aj = rA[j], bj = rB[j], Ej = rE[j];
                const int e0 = sFoff[j], e1 = sFoff[j + 1];
                float sL = 0.0f, Pj = 0.0f;
                for (int e = e0; e < e1; e++) {
                    int k = sFent[e];
                    sL += Lc[k]; Pj += gC[k];
                }
                float EoRT = Ej * invRT;
                float r = Aj * expf(bj * sLnT - EoRT + sL);
                r_[j]  = r;
                rP_[j] = r * Pj;
                rT_[j] = (r * invT) * (bj + EoRT - Pj);
            }
            __syncthreads();

            // ---- P5: three parallel gathers (wd owners / uu / vv) ----
            if (own) {
                const int e0 = sNoff[tid], em = sNmid[tid], e1 = sNoff[tid + 1];
                float qp = 0.0f, qn = 0.0f;
                for (int e = e0; e < em; e++) qp += r_[sNent[e]];
                for (int e = em; e < e1; e++) qn += r_[sNent[e]];
                wdk = qp - qn;
                Gk = Y - ycur - dt * wdk * Work;
                zz[tid]   = t0ak * mYk * Gk;
                tsig[tid] = sm0k * mYk * Gk;
                tcpx[tid] = cpwk * Gk;
                tH[tid]   = hmolk * wdk;
                thw[tid]  = cpRk * wdk;
            } else if (tid >= NS && tid < 2 * NS) {
                const int k = tid - NS;
                const int e0 = sNoff[k], em = sNmid[k], e1 = sNoff[k + 1];
                float qp = 0.0f, qn = 0.0f;
                for (int e = e0; e < em; e++) qp += rP_[sNent[e]];
                for (int e = em; e < e1; e++) qn += rP_[sNent[e]];
                float u = qp - qn;
                uu_s[k] = u;
                thu[k]  = hmol_s[k] * u;
            } else if (tid >= 2 * NS && tid < 3 * NS) {
                const int k = tid - 2 * NS;
                const int e0 = sNoff[k], em = sNmid[k], e1 = sNoff[k + 1];
                float qp = 0.0f, qn = 0.0f;
                for (int e = e0; e < em; e++) qp += rT_[sNent[e]];
                for (int e = em; e < e1; e++) qn += rT_[sNent[e]];
                float v = qp - qn;
                vv_s[k] = v;
                thv[k]  = hmol_s[k] * v;
            }
            __syncthreads();

            // ---- P6: warp0 scalar reductions; warps 1..4 compute w_ ----
            if (tid < 32) {
                float cp = wred53(tcp, lane);
                float H  = wred53(tH, lane);
                float hu = wred53(thu, lane);
                float hv = wred53(thv, lane);
                float hw = wred53(thw, lane);
                float dc = wred53(tdc, lane);
                float sg = wred53(tsig, lane);
                float cx = wred53(tcpx, lane);
                if (lane == 0) {
                    float cpm = RGAS * cp;
                    float rcp = rho * cpm;
                    float dTv = -H / rcp;
                    sHu = hu; sSig = sg; sCpx = cx;
                    sC1 = -dt / rcp;
                    sC2 = -dt * dTv;
                    sC3 = -dt * dTv / cpm;
                    float J00 = sMT * (-(RGAS * hw + hv) / rcp
                                       - dTv * (-invT + RGAS * dc / cpm));
                    sC4 = dt * J00;
                    sG0 = sYn0 - sYcur0 - dt * dTv;
                }
            } else {
                for (int j = tid - 32; j < NRX; j += BD - 32) {
                    const int e0 = sFoff[j], e1 = sFoff[j + 1];
                    float s = 0.0f;
                    for (int e = e0; e < e1; e++) s += zz[sFent[e]];
                    w_[j] = r_[j] * s;
                }
            }
            __syncthreads();

            // ---- P7: owners: q gather + state update ----
            if (own) {
                const int e0 = sNoff[tid], em = sNmid[tid], e1 = sNoff[tid + 1];
                float qp = 0.0f, qn = 0.0f;
                for (int e = e0; e < em; e++) qp += w_[sNent[e]];
                for (int e = em; e < e1; e++) qn += w_[sNent[e]];
                float q = qp - qn;
                float u = uu_s[tid], v = vv_s[tid];
                float a1 = dt * Work * (u - wdk);
                float a2 = dt * Work;
                float a3 = dt * sMT * Work * (v + wdk * invT);
                float xk = Gk + a1 * sSig + a2 * q + a3 * sG0;
                thq[tid] = hmolk * q;
                Y -= xk;
            }
            __syncthreads();

            // ---- P8: warp0: x0 + T state + next-Newton T prep ----
            if (tid < 32) {
                float hq = wred53(thq, lane);
                if (lane == 0) {
                    float x0 = sG0 + sC1 * (sHu * sSig + hq)
                             + sC2 * sSig + sC3 * sCpx + sC4 * sG0;
                    float t = sYn0 - x0;
                    sYn0 = t;
                    float Tc = fminf(fmaxf(t, 200.0f), 5000.0f);
                    sT = Tc;
                    sMT = (t > 200.0f && t < 5000.0f) ? 1.0f : 0.0f;
                    sLnT = logf(Tc);
                }
            }
            __syncthreads();
        } // newton
    } // steps

    if (own) out[b * ND + 1 + tid] = Y;
    if (tid == 0) out[b * ND] = sYn0;
}

extern "C" void kernel_launch(void* const* d_in, const int* in_sizes, int n_in,
                              void* d_out, int out_size) {
    const float* T0  = (const float*)d_in[0];
    const float* P   = (const float*)d_in[1];
    const float* Y0  = (const float*)d_in[2];
    const float* W   = (const float*)d_in[3];
    const float* nlo = (const float*)d_in[4];
    const float* nhi = (const float*)d_in[5];
    const float* Tm  = (const float*)d_in[6];
    const float* A   = (const float*)d_in[7];
    const float* Bc  = (const float*)d_in[8];
    const float* E   = (const float*)d_in[9];
    const float* nf  = (const float*)d_in[10];
    const float* nb  = (const float*)d_in[11];
    const int*   ns  = (const int*)d_in[12];
    const int B = in_sizes[0];

    prep_csr_kernel<<<1, 256>>>(nf, nb);
    reactor_kernel<<<B, BD>>>(T0, P, Y0, W, nlo, nhi, Tm, A, Bc, E, ns, (float*)d_out);
}

// round 15
// speedup vs baseline: 1.1165x; 1.1165x over previous
#include <cuda_runtime.h>

#define NS    53       // species
#define ND    54       // state dim
#define NRX   325      // reactions
#define FCAP  1024     // fwd CSR entries cap (expected ~690)
#define NCAP  2048     // net CSR entries cap (expected ~1365)
#define BD    192      // threads per block
#define RGAS  8.314462618f

// ---- CSRs built once per launch. Stoichiometry is exactly 0/1:
//      fwd lists carry no values; net lists are split pos-run / neg-run ----
__device__ int   g_foff[NRX + 1];
__device__ short g_fent[FCAP];
__device__ int   g_noff[NS + 1];
__device__ int   g_nmid[NS];
__device__ short g_nent[NCAP];

// Stage both stoich tables in smem (coalesced), then count/scan/fill from smem.
__global__ void prep_csr_kernel(const float* __restrict__ nuf,
                                const float* __restrict__ nub) {
    __shared__ signed char fF[NRX * NS];
    __shared__ signed char sg[NRX * NS];
    __shared__ int scf[NRX], scp[NS], scn[NS];
    const int tid = threadIdx.x;   // single block, 256 threads
    for (int i = tid; i < NRX * NS; i += 256) {
        float f = nuf[i];
        float net = nub[i] - f;
        fF[i] = (f != 0.0f) ? 1 : 0;
        sg[i] = (net > 0.0f) ? 1 : ((net < 0.0f) ? -1 : 0);
    }
    __syncthreads();
    for (int j = tid; j < NRX; j += 256) {
        int c = 0;
        for (int k = 0; k < NS; k++) c += fF[j * NS + k];
        scf[j] = c;
    }
    for (int s = tid; s < NS; s += 256) {
        int cp = 0, cn = 0;
        for (int j = 0; j < NRX; j++) {
            int v = sg[j * NS + s];
            cp += (v > 0); cn += (v < 0);
        }
        scp[s] = cp; scn[s] = cn;
    }
    __syncthreads();
    if (tid == 0) {
        int run = 0;
        for (int i = 0; i < NRX; i++) { g_foff[i] = run; run += scf[i]; }
        g_foff[NRX] = run;
    }
    if (tid == 32) {
        int run = 0;
        for (int i = 0; i < NS; i++) {
            g_noff[i] = run;
            g_nmid[i] = run + scp[i];
            run += scp[i] + scn[i];
        }
        g_noff[NS] = run;
    }
    __syncthreads();
    for (int j = tid; j < NRX; j += 256) {
        int w = g_foff[j];
        for (int k = 0; k < NS; k++)
            if (fF[j * NS + k] && w < FCAP) g_fent[w++] = (short)k;
    }
    for (int s = tid; s < NS; s += 256) {
        int wp = g_noff[s], wn = g_nmid[s];
        for (int j = 0; j < NRX; j++) {
            int v = sg[j * NS + s];
            if (v > 0 && wp < NCAP) g_nent[wp++] = (short)j;
            else if (v < 0 && wn < NCAP) g_nent[wn++] = (short)j;
        }
    }
}

__device__ __forceinline__ float wred53(const float* a, int lane) {
    float s = (lane < NS ? a[lane] : 0.0f)
            + (lane + 32 < NS ? a[lane + 32] : 0.0f);
    #pragma unroll
    for (int o = 16; o; o >>= 1) s += __shfl_xor_sync(0xffffffffu, s, o);
    return s;
}

__global__ __launch_bounds__(BD, 7)
void reactor_kernel(const float* __restrict__ T0,  const float* __restrict__ Pv,
                    const float* __restrict__ Y0,  const float* __restrict__ Wm,
                    const float* __restrict__ nlo, const float* __restrict__ nhi,
                    const float* __restrict__ Tmid,
                    const float* __restrict__ rA,  const float* __restrict__ rB,
                    const float* __restrict__ rE,  const int* __restrict__ nstp,
                    float* __restrict__ out) {
    __shared__ float Lc[NS], gC[NS], hmol_s[NS], uu_s[NS], vv_s[NS], zz[NS];
    __shared__ float tmw[NS], tcp[NS], tdc[NS], tH[NS], thw[NS];
    __shared__ float tsig[NS], tcpx[NS], thu[NS], thv[NS], thq[NS];
    __shared__ float r_[NRX], rP_[NRX], rT_[NRX], w_[NRX];
    __shared__ unsigned short sFoff[NRX + 1];
    __shared__ short sFent[FCAP];
    __shared__ unsigned short sNoff[NS + 1];
    __shared__ unsigned short sNmid[NS];
    __shared__ short sNent[NCAP];
    __shared__ float sT, sLnT, sMT, sRho, sInvRho, sInvIMW, sYn0, sYcur0;
    __shared__ float sSig, sCpx, sG0, sHu, sC1, sC2, sC3, sC4;

    const int tid  = threadIdx.x;
    const int lane = tid & 31;
    const int b    = blockIdx.x;
    const bool own = (tid < NS);

    const float P = Pv[0];
    const int n_steps = nstp[0];
    const float dt = 1.0e-6f / (float)n_steps;

    // ---- one-time: CSRs to smem, owner state ----
    for (int i = tid; i < NRX + 1; i += BD) sFoff[i] = (unsigned short)g_foff[i];
    for (int i = tid; i < FCAP; i += BD)    sFent[i] = g_fent[i];
    for (int i = tid; i < NS + 1; i += BD)  sNoff[i] = (unsigned short)g_noff[i];
    for (int i = tid; i < NS; i += BD)      sNmid[i] = (unsigned short)g_nmid[i];
    for (int i = tid; i < NCAP; i += BD)    sNent[i] = g_nent[i];

    float Y = 0.0f, ycur = 0.0f, Wsk = 1.0f, iw = 1.0f, Tmk = 0.0f;
    if (own) {
        Wsk = Wm[tid];
        iw  = 1.0f / Wsk;
        Y   = Y0[b * NS + tid];
        Tmk = Tmid[tid];
    }
    if (tid == 0) {
        float t = T0[b];
        sYn0 = t;
        float Tc = fminf(fmaxf(t, 200.0f), 5000.0f);
        sT = Tc;
        sMT = (t > 200.0f && t < 5000.0f) ? 1.0f : 0.0f;
        sLnT = logf(Tc);
    }
    __syncthreads();

    for (int step = 0; step < n_steps; ++step) {
        for (int it = 0; it < 2; ++it) {
            const float T = sT;
            const float invT = 1.0f / T;
            float Yc = 0.0f, mYk = 0.0f, cpRk = 0.0f, hmolk = 0.0f;
            float t0ak = 0.0f, Work = 0.0f, sm0k = 0.0f, cpwk = 0.0f;
            float Gk = 0.0f, wdk = 0.0f;

            // ---- P1: thermo (owners) ----
            if (own) {
                if (it == 0) ycur = Y;
                float Yr = Y;
                Yc  = fminf(fmaxf(Yr, 0.0f), 1.0f);
                mYk = (Yr > 0.0f && Yr < 1.0f) ? 1.0f : 0.0f;
                const float* a = (T < Tmk) ? (nlo + 7 * tid) : (nhi + 7 * tid);
                float a0 = a[0], a1v = a[1], a2v = a[2], a3v = a[3], a4 = a[4], a5 = a[5];
                float T2 = T * T, T3 = T2 * T, T4 = T2 * T2;
                cpRk = a0 + a1v * T + a2v * T2 + a3v * T3 + a4 * T4;
                float hRT = a0 + a1v * T * 0.5f + a2v * T2 * (1.0f / 3.0f)
                          + a3v * T3 * 0.25f + a4 * T4 * 0.2f + a5 * invT;
                hmolk = hRT * RGAS * T;
                float dcpRk = a1v + 2.0f * a2v * T + 3.0f * a3v * T2 + 4.0f * a4 * T3;
                float yw = Yc * iw;
                tmw[tid] = yw;
                tcp[tid] = yw * cpRk;
                tdc[tid] = yw * dcpRk;
                hmol_s[tid] = hmolk;
            }
            __syncthreads();

            // ---- P2: mixture reduction (warp0) ----
            if (tid < 32) {
                float s = wred53(tmw, lane);
                if (lane == 0) {
                    sInvIMW = 1.0f / s;
                    sRho = P / (RGAS * T * s);
                    sInvRho = (RGAS * T * s) / P;
                }
            }
            __syncthreads();

            // ---- P3: concentrations (owners) ----
            const float rho = sRho, invRho = sInvRho, invIMW = sInvIMW;
            if (own) {
                float C  = rho * Yc * iw;
                float Ce = C + 1e-30f;
                Lc[tid] = logf(Ce);
                gC[tid] = C / Ce;
                t0ak = rho * iw / Ce;
                Work = Wsk * invRho;
                sm0k = -invIMW * iw;
                cpwk = cpRk * RGAS * iw * mYk;
            }
            __syncthreads();

            // ---- P4: rates (all threads); single fused exp ----
            const float invRT = 1.0f / (RGAS * T);
            for (int j = tid; j < NRX; j += BD) {
                float Aj = rA[j], bj = rB[j], Ej = rE[j];
                const int e0 = sFoff[j], e1 = sFoff[j + 1];
                float sL = 0.0f, Pj = 0.0f;
                for (int e = e0; e < e1; e++) {
                    int k = sFent[e];
                    sL += Lc[k]; Pj += gC[k];
                }
                float EoRT = Ej * invRT;
                float r = Aj * expf(bj * sLnT - EoRT + sL);
                r_[j]  = r;
                rP_[j] = r * Pj;
                rT_[j] = (r * invT) * (bj + EoRT - Pj);
            }
            __syncthreads();

            // ---- P5: gathers (wd owners / uu / vv) + G + sweep inputs ----
            if (own) {
                const int e0 = sNoff[tid], em = sNmid[tid], e1 = sNoff[tid + 1];
                float qp = 0.0f, qn = 0.0f;
                for (int e = e0; e < em; e++) qp += r_[sNent[e]];
                for (int e = em; e < e1; e++) qn += r_[sNent[e]];
                wdk = qp - qn;
                Gk = Y - ycur - dt * wdk * Work;
                zz[tid]   = t0ak * mYk * Gk;
                tsig[tid] = sm0k * mYk * Gk;
                tcpx[tid] = cpwk * Gk;
                tH[tid]   = hmolk * wdk;
                thw[tid]  = cpRk * wdk;
            } else if (tid >= 64 && tid < 64 + NS) {
                const int k = tid - 64;
                const int e0 = sNoff[k], em = sNmid[k], e1 = sNoff[k + 1];
                float qp = 0.0f, qn = 0.0f;
                for (int e = e0; e < em; e++) qp += rP_[sNent[e]];
                for (int e = em; e < e1; e++) qn += rP_[sNent[e]];
                float u = qp - qn;
                uu_s[k] = u;
                thu[k]  = hmol_s[k] * u;
            } else if (tid >= 128 && tid < 128 + NS) {
                const int k = tid - 128;
                const int e0 = sNoff[k], em = sNmid[k], e1 = sNoff[k + 1];
                float qp = 0.0f, qn = 0.0f;
                for (int e = e0; e < em; e++) qp += rT_[sNent[e]];
                for (int e = em; e < e1; e++) qn += rT_[sNent[e]];
                float v = qp - qn;
                vv_s[k] = v;
                thv[k]  = hmol_s[k] * v;
            }
            __syncthreads();

            // ---- P6: warp0: 8 reductions + coefficients; warps 1..5: w_ ----
            if (tid < 32) {
                float cp = wred53(tcp, lane);
                float H  = wred53(tH, lane);
                float hu = wred53(thu, lane);
                float hv = wred53(thv, lane);
                float hw = wred53(thw, lane);
                float dc = wred53(tdc, lane);
                float sg = wred53(tsig, lane);
                float cx = wred53(tcpx, lane);
                if (lane == 0) {
                    if (it == 0) sYcur0 = sYn0;
                    float cpm = RGAS * cp;
                    float rcp = rho * cpm;
                    float dTv = -H / rcp;
                    sHu = hu; sSig = sg; sCpx = cx;
                    sC1 = -dt / rcp;
                    sC2 = -dt * dTv;
                    sC3 = -dt * dTv / cpm;
                    float J00 = sMT * (-(RGAS * hw + hv) / rcp
                                       - dTv * (-invT + RGAS * dc / cpm));
                    sC4 = dt * J00;
                    sG0 = sYn0 - sYcur0 - dt * dTv;
                }
            } else {
                for (int j = tid - 32; j < NRX; j += BD - 32) {
                    const int e0 = sFoff[j], e1 = sFoff[j + 1];
                    float s = 0.0f;
                    for (int e = e0; e < e1; e++) s += zz[sFent[e]];
                    w_[j] = r_[j] * s;
                }
            }
            __syncthreads();

            // ---- P7 (C): owners: q gather + fused state update ----
            if (own) {
                const int e0 = sNoff[tid], em = sNmid[tid], e1 = sNoff[tid + 1];
                float qp = 0.0f, qn = 0.0f;
                for (int e = e0; e < em; e++) qp += w_[sNent[e]];
                for (int e = em; e < e1; e++) qn += w_[sNent[e]];
                float q = qp - qn;
                float a1 = dt * Work * (uu_s[tid] - wdk);
                float a2 = dt * Work;
                float a3 = dt * sMT * Work * (vv_s[tid] + wdk * invT);
                float xk = Gk + a1 * sSig + a2 * q + a3 * sG0;
                thq[tid] = hmolk * q;
                Y -= xk;
            }
            __syncthreads();

            // ---- P8 (D): warp0: x0 + T update + next-Newton T prep ----
            if (tid < 32) {
                float hq = wred53(thq, lane);
                if (lane == 0) {
                    float x0 = sG0 + sC1 * (sHu * sSig + hq)
                             + sC2 * sSig + sC3 * sCpx + sC4 * sG0;
                    float t = sYn0 - x0;
                    sYn0 = t;
                    float Tc = fminf(fmaxf(t, 200.0f), 5000.0f);
                    sT = Tc;
                    sMT = (t > 200.0f && t < 5000.0f) ? 1.0f : 0.0f;
                    sLnT = logf(Tc);
                }
            }
            __syncthreads();
        } // newton
    } // steps

    if (own) out[b * ND + 1 + tid] = Y;
    if (tid == 0) out[b * ND] = sYn0;
}

extern "C" void kernel_launch(void* const* d_in, const int* in_sizes, int n_in,
                              void* d_out, int out_size) {
    const float* T0  = (const float*)d_in[0];
    const float* P   = (const float*)d_in[1];
    const float* Y0  = (const float*)d_in[2];
    const float* W   = (const float*)d_in[3];
    const float* nlo = (const float*)d_in[4];
    const float* nhi = (const float*)d_in[5];
    const float* Tm  = (const float*)d_in[6];
    const float* A   = (const float*)d_in[7];
    const float* Bc  = (const float*)d_in[8];
    const float* E   = (const float*)d_in[9];
    const float* nf  = (const float*)d_in[10];
    const float* nb  = (const float*)d_in[11];
    const int*   ns  = (const int*)d_in[12];
    const int B = in_sizes[0];

    prep_csr_kernel<<<1, 256>>>(nf, nb);
    reactor_kernel<<<B, BD>>>(T0, P, Y0, W, nlo, nhi, Tm, A, Bc, E, ns, (float*)d_out);
}

// round 16
// speedup vs baseline: 1.3245x; 1.1863x over previous
#include <cuda_runtime.h>

#define NS    53       // species
#define ND    54       // state dim
#define NRX   325      // reactions
#define FCAP  2048     // fwd CSR entries cap (padded-even runs)
#define NCAP  2048     // net CSR entries cap (padded-even runs)
#define BD    192      // threads per block
#define RGAS  8.314462618f

// ---- CSRs built once per launch. Stoichiometry is exactly 0/1.
//      All runs padded to EVEN length; dummy fwd entry = NS, dummy net = NRX ----
__device__ int   g_foff[NRX + 1];
__device__ short g_fent[FCAP];
__device__ int   g_noff[NS + 1];
__device__ int   g_nmid[NS];
__device__ short g_nent[NCAP];

__global__ void prep_csr_kernel(const float* __restrict__ nuf,
                                const float* __restrict__ nub) {
    __shared__ signed char fF[NRX * NS];
    __shared__ signed char sg[NRX * NS];
    __shared__ int scf[NRX], scp[NS], scn[NS];
    const int tid = threadIdx.x;   // single block, 256 threads
    for (int i = tid; i < NRX * NS; i += 256) {
        float f = nuf[i];
        float net = nub[i] - f;
        fF[i] = (f != 0.0f) ? 1 : 0;
        sg[i] = (net > 0.0f) ? 1 : ((net < 0.0f) ? -1 : 0);
    }
    __syncthreads();
    for (int j = tid; j < NRX; j += 256) {
        int c = 0;
        for (int k = 0; k < NS; k++) c += fF[j * NS + k];
        scf[j] = c;
    }
    for (int s = tid; s < NS; s += 256) {
        int cp = 0, cn = 0;
        for (int j = 0; j < NRX; j++) {
            int v = sg[j * NS + s];
            cp += (v > 0); cn += (v < 0);
        }
        scp[s] = cp; scn[s] = cn;
    }
    __syncthreads();
    if (tid == 0) {
        int run = 0;
        for (int i = 0; i < NRX; i++) {
            g_foff[i] = run;
            run += (scf[i] + 1) & ~1;          // pad even
        }
        g_foff[NRX] = run;
    }
    if (tid == 32) {
        int run = 0;
        for (int i = 0; i < NS; i++) {
            int cp2 = (scp[i] + 1) & ~1;
            int cn2 = (scn[i] + 1) & ~1;
            g_noff[i] = run;
            g_nmid[i] = run + cp2;
            run += cp2 + cn2;
        }
        g_noff[NS] = run;
    }
    __syncthreads();
    for (int j = tid; j < NRX; j += 256) {
        int w = g_foff[j];
        for (int k = 0; k < NS; k++)
            if (fF[j * NS + k] && w < FCAP) g_fent[w++] = (short)k;
        if ((w & 1) && w < FCAP) g_fent[w++] = (short)NS;       // dummy species
    }
    for (int s = tid; s < NS; s += 256) {
        int wp = g_noff[s], wn = g_nmid[s];
        for (int j = 0; j < NRX; j++) {
            int v = sg[j * NS + s];
            if (v > 0 && wp < NCAP) g_nent[wp++] = (short)j;
            else if (v < 0 && wn < NCAP) g_nent[wn++] = (short)j;
        }
        if ((wp & 1) && wp < NCAP) g_nent[wp++] = (short)NRX;   // dummy reaction
        if ((wn & 1) && wn < NCAP) g_nent[wn++] = (short)NRX;
    }
}

__device__ __forceinline__ float wred53(const float* a, int lane) {
    float s = (lane < NS ? a[lane] : 0.0f)
            + (lane + 32 < NS ? a[lane + 32] : 0.0f);
    #pragma unroll
    for (int o = 16; o; o >>= 1) s += __shfl_xor_sync(0xffffffffu, s, o);
    return s;
}

__global__ __launch_bounds__(BD, 7)
void reactor_kernel(const float* __restrict__ T0,  const float* __restrict__ Pv,
                    const float* __restrict__ Y0,  const float* __restrict__ Wm,
                    const float* __restrict__ nlo, const float* __restrict__ nhi,
                    const float* __restrict__ Tmid,
                    const float* __restrict__ rA,  const float* __restrict__ rB,
                    const float* __restrict__ rE,  const int* __restrict__ nstp,
                    float* __restrict__ out) {
    __shared__ float2 LG[NS + 1];               // (Lc, gC), dummy slot NS = (0,0)
    __shared__ float hmol_s[NS], uu_s[NS], vv_s[NS];
    __shared__ float zz[NS + 1];                // dummy slot NS = 0
    __shared__ float tmw[NS], tcp[NS], tdc[NS], tH[NS], thw[NS];
    __shared__ float tsig[NS], tcpx[NS], thu[NS], thv[NS], thq[NS];
    __shared__ float r_[NRX + 1];               // dummy slot NRX = 0
    __shared__ float2 rPT_[NRX + 1];            // (rP, rT), dummy = (0,0)
    __shared__ float w_[NRX + 1];               // dummy = 0
    __shared__ unsigned short sFoff[NRX + 1];
    __shared__ unsigned int fPair[FCAP / 2];
    __shared__ unsigned short sNoff[NS + 1];
    __shared__ unsigned short sNmid[NS];
    __shared__ unsigned int nPair[NCAP / 2];
    __shared__ float sT, sLnT, sMT, sRho, sInvRho, sInvIMW, sYn0, sYcur0;
    __shared__ float sSig, sCpx, sG0, sHu, sC1, sC2, sC3, sC4;

    const int tid  = threadIdx.x;
    const int lane = tid & 31;
    const int b    = blockIdx.x;
    const bool own = (tid < NS);

    const float P = Pv[0];
    const int n_steps = nstp[0];
    const float dt = 1.0e-6f / (float)n_steps;

    // ---- one-time: CSRs to smem (paired), init dummies + state ----
    for (int i = tid; i < NRX + 1; i += BD) sFoff[i] = (unsigned short)g_foff[i];
    {
        const unsigned int* gf = (const unsigned int*)g_fent;
        const unsigned int* gn = (const unsigned int*)g_nent;
        for (int i = tid; i < FCAP / 2; i += BD) fPair[i] = gf[i];
        for (int i = tid; i < NCAP / 2; i += BD) nPair[i] = gn[i];
    }
    for (int i = tid; i < NS + 1; i += BD)  sNoff[i] = (unsigned short)g_noff[i];
    for (int i = tid; i < NS; i += BD)      sNmid[i] = (unsigned short)g_nmid[i];
    if (tid == BD - 1) {
        LG[NS] = make_float2(0.0f, 0.0f);
        zz[NS] = 0.0f;
        r_[NRX] = 0.0f;
        rPT_[NRX] = make_float2(0.0f, 0.0f);
        w_[NRX] = 0.0f;
    }

    float Y = 0.0f, ycur = 0.0f, Wsk = 1.0f, iw = 1.0f, Tmk = 0.0f;
    if (own) {
        Wsk = Wm[tid];
        iw  = 1.0f / Wsk;
        Y   = Y0[b * NS + tid];
        Tmk = Tmid[tid];
    }
    if (tid == 0) {
        float t = T0[b];
        sYn0 = t;
        float Tc = fminf(fmaxf(t, 200.0f), 5000.0f);
        sT = Tc;
        sMT = (t > 200.0f && t < 5000.0f) ? 1.0f : 0.0f;
        sLnT = logf(Tc);
    }
    __syncthreads();

    for (int step = 0; step < n_steps; ++step) {
        for (int it = 0; it < 2; ++it) {
            const float T = sT;
            const float invT = 1.0f / T;
            float Yc = 0.0f, mYk = 0.0f, cpRk = 0.0f, hmolk = 0.0f;
            float t0ak = 0.0f, Work = 0.0f, sm0k = 0.0f, cpwk = 0.0f;
            float Gk = 0.0f, wdk = 0.0f;

            // ---- P1: thermo (owners) ----
            if (own) {
                if (it == 0) ycur = Y;
                float Yr = Y;
                Yc  = fminf(fmaxf(Yr, 0.0f), 1.0f);
                mYk = (Yr > 0.0f && Yr < 1.0f) ? 1.0f : 0.0f;
                const float* a = (T < Tmk) ? (nlo + 7 * tid) : (nhi + 7 * tid);
                float a0 = a[0], a1v = a[1], a2v = a[2], a3v = a[3], a4 = a[4], a5 = a[5];
                float T2 = T * T, T3 = T2 * T, T4 = T2 * T2;
                cpRk = a0 + a1v * T + a2v * T2 + a3v * T3 + a4 * T4;
                float hRT = a0 + a1v * T * 0.5f + a2v * T2 * (1.0f / 3.0f)
                          + a3v * T3 * 0.25f + a4 * T4 * 0.2f + a5 * invT;
                hmolk = hRT * RGAS * T;
                float dcpRk = a1v + 2.0f * a2v * T + 3.0f * a3v * T2 + 4.0f * a4 * T3;
                float yw = Yc * iw;
                tmw[tid] = yw;
                tcp[tid] = yw * cpRk;
                tdc[tid] = yw * dcpRk;
                hmol_s[tid] = hmolk;
            }
            __syncthreads();

            // ---- P2: mixture reduction (warp0) ----
            if (tid < 32) {
                float s = wred53(tmw, lane);
                if (lane == 0) {
                    sInvIMW = 1.0f / s;
                    sRho = P / (RGAS * T * s);
                    sInvRho = (RGAS * T * s) / P;
                }
            }
            __syncthreads();

            // ---- P3: concentrations (owners) ----
            const float rho = sRho, invRho = sInvRho, invIMW = sInvIMW;
            if (own) {
                float C  = rho * Yc * iw;
                float Ce = C + 1e-30f;
                LG[tid] = make_float2(logf(Ce), C / Ce);
                t0ak = rho * iw / Ce;
                Work = Wsk * invRho;
                sm0k = -invIMW * iw;
                cpwk = cpRk * RGAS * iw * mYk;
            }
            __syncthreads();

            // ---- P4: rates (all threads); single fused exp; paired fwd walk ----
            const float invRT = 1.0f / (RGAS * T);
            for (int j = tid; j < NRX; j += BD) {
                float Aj = rA[j], bj = rB[j], Ej = rE[j];
                const int h0 = sFoff[j] >> 1, h1 = sFoff[j + 1] >> 1;
                float sL = 0.0f, Pj = 0.0f;
                for (int h = h0; h < h1; h++) {
                    unsigned int pr = fPair[h];
                    float2 g0 = LG[pr & 0xffffu];
                    float2 g1 = LG[pr >> 16];
                    sL += g0.x + g1.x;
                    Pj += g0.y + g1.y;
                }
                float EoRT = Ej * invRT;
                float r = Aj * expf(bj * sLnT - EoRT + sL);
                r_[j] = r;
                rPT_[j] = make_float2(r * Pj, (r * invT) * (bj + EoRT - Pj));
            }
            __syncthreads();

            // ---- P5: owners: wd walk; group2: merged uu+vv walk ----
            if (own) {
                const int h0 = sNoff[tid] >> 1, hm = sNmid[tid] >> 1,
                          h1 = sNoff[tid + 1] >> 1;
                float qp = 0.0f, qn = 0.0f;
                for (int h = h0; h < hm; h++) {
                    unsigned int pr = nPair[h];
                    qp += r_[pr & 0xffffu] + r_[pr >> 16];
                }
                for (int h = hm; h < h1; h++) {
                    unsigned int pr = nPair[h];
                    qn += r_[pr & 0xffffu] + r_[pr >> 16];
                }
                wdk = qp - qn;
                Gk = Y - ycur - dt * wdk * Work;
                zz[tid]   = t0ak * mYk * Gk;
                tsig[tid] = sm0k * mYk * Gk;
                tcpx[tid] = cpwk * Gk;
                tH[tid]   = hmolk * wdk;
                thw[tid]  = cpRk * wdk;
            } else if (tid >= 64 && tid < 64 + NS) {
                const int k = tid - 64;
                const int h0 = sNoff[k] >> 1, hm = sNmid[k] >> 1,
                          h1 = sNoff[k + 1] >> 1;
                float up = 0.0f, vp = 0.0f, un = 0.0f, vn = 0.0f;
                for (int h = h0; h < hm; h++) {
                    unsigned int pr = nPair[h];
                    float2 a = rPT_[pr & 0xffffu];
                    float2 c = rPT_[pr >> 16];
                    up += a.x + c.x; vp += a.y + c.y;
                }
                for (int h = hm; h < h1; h++) {
                    unsigned int pr = nPair[h];
                    float2 a = rPT_[pr & 0xffffu];
                    float2 c = rPT_[pr >> 16];
                    un += a.x + c.x; vn += a.y + c.y;
                }
                float u = up - un, v = vp - vn;
                uu_s[k] = u; vv_s[k] = v;
                float hm_ = hmol_s[k];
                thu[k] = hm_ * u;
                thv[k] = hm_ * v;
            }
            __syncthreads();

            // ---- P6: warp0: 8 reductions + coefficients; warps 1..5: w_ ----
            if (tid < 32) {
                float cp = wred53(tcp, lane);
                float H  = wred53(tH, lane);
                float hu = wred53(thu, lane);
                float hv = wred53(thv, lane);
                float hw = wred53(thw, lane);
                float dc = wred53(tdc, lane);
                float sg = wred53(tsig, lane);
                float cx = wred53(tcpx, lane);
                if (lane == 0) {
                    if (it == 0) sYcur0 = sYn0;
                    float cpm = RGAS * cp;
                    float rcp = rho * cpm;
                    float dTv = -H / rcp;
                    sHu = hu; sSig = sg; sCpx = cx;
                    sC1 = -dt / rcp;
                    sC2 = -dt * dTv;
                    sC3 = -dt * dTv / cpm;
                    float J00 = sMT * (-(RGAS * hw + hv) / rcp
                                       - dTv * (-invT + RGAS * dc / cpm));
                    sC4 = dt * J00;
                    sG0 = sYn0 - sYcur0 - dt * dTv;
                }
            } else {
                for (int j = tid - 32; j < NRX; j += BD - 32) {
                    const int h0 = sFoff[j] >> 1, h1 = sFoff[j + 1] >> 1;
                    float s = 0.0f;
                    for (int h = h0; h < h1; h++) {
                        unsigned int pr = fPair[h];
                        s += zz[pr & 0xffffu] + zz[pr >> 16];
                    }
                    w_[j] = r_[j] * s;
                }
            }
            __syncthreads();

            // ---- P7: owners: q walk + fused state update ----
            if (own) {
                const int h0 = sNoff[tid] >> 1, hm = sNmid[tid] >> 1,
                          h1 = sNoff[tid + 1] >> 1;
                float qp = 0.0f, qn = 0.0f;
                for (int h = h0; h < hm; h++) {
                    unsigned int pr = nPair[h];
                    qp += w_[pr & 0xffffu] + w_[pr >> 16];
                }
                for (int h = hm; h < h1; h++) {
                    unsigned int pr = nPair[h];
                    qn += w_[pr & 0xffffu] + w_[pr >> 16];
                }
                float q = qp - qn;
                float a1 = dt * Work * (uu_s[tid] - wdk);
                float a2 = dt * Work;
                float a3 = dt * sMT * Work * (vv_s[tid] + wdk * invT);
                float xk = Gk + a1 * sSig + a2 * q + a3 * sG0;
                thq[tid] = hmolk * q;
                Y -= xk;
            }
            __syncthreads();

            // ---- P8: warp0: x0 + T update + next-Newton T prep ----
            if (tid < 32) {
                float hq = wred53(thq, lane);
                if (lane == 0) {
                    float x0 = sG0 + sC1 * (sHu * sSig + hq)
                             + sC2 * sSig + sC3 * sCpx + sC4 * sG0;
                    float t = sYn0 - x0;
                    sYn0 = t;
                    float Tc = fminf(fmaxf(t, 200.0f), 5000.0f);
                    sT = Tc;
                    sMT = (t > 200.0f && t < 5000.0f) ? 1.0f : 0.0f;
                    sLnT = logf(Tc);
                }
            }
            __syncthreads();
        } // newton
    } // steps

    if (own) out[b * ND + 1 + tid] = Y;
    if (tid == 0) out[b * ND] = sYn0;
}

extern "C" void kernel_launch(void* const* d_in, const int* in_sizes, int n_in,
                              void* d_out, int out_size) {
    const float* T0  = (const float*)d_in[0];
    const float* P   = (const float*)d_in[1];
    const float* Y0  = (const float*)d_in[2];
    const float* W   = (const float*)d_in[3];
    const float* nlo = (const float*)d_in[4];
    const float* nhi = (const float*)d_in[5];
    const float* Tm  = (const float*)d_in[6];
    const float* A   = (const float*)d_in[7];
    const float* Bc  = (const float*)d_in[8];
    const float* E   = (const float*)d_in[9];
    const float* nf  = (const float*)d_in[10];
    const float* nb  = (const float*)d_in[11];
    const int*   ns  = (const int*)d_in[12];
    const int B = in_sizes[0];

    prep_csr_kernel<<<1, 256>>>(nf, nb);
    reactor_kernel<<<B, BD>>>(T0, P, Y0, W, nlo, nhi, Tm, A, Bc, E, ns, (float*)d_out);
}